// round 9
// baseline (speedup 1.0000x reference)
#include <cuda_runtime.h>
#include <cuda_bf16.h>

#define NB 16384
#define LL 1024
#define ROWS_PER_BLK 8
#define GRID (NB / ROWS_PER_BLK)   // 2048

__device__ double       g_acc   = 0.0;  // 0 at kernel entry; winner restores
__device__ unsigned int g_count = 0;    // ditto

__global__ __launch_bounds__(256) void bicut_fused(
    const float4* __restrict__ out4,   // output as float4: row stride 512
    const int4*   __restrict__ lab4,   // labels (int32) as int4: row stride 256
    float*        __restrict__ out)
{
    const int tid  = threadIdx.x;
    const int wid  = tid >> 5;
    const int lane = tid & 31;
    const int row  = blockIdx.x * ROWS_PER_BLK + wid;

    const float4* orow = out4 + (size_t)row * 512;
    const int4*   lrow = lab4 + (size_t)row * 256;

    // ---- front-batch the entire row into registers (MLP = 24/warp) ----
    float4 A[16];   // 8 chunks x 2 float4: elements j = 128c + 4*lane + {0..3}
    int4   L[8];    // labels for the same j's
    #pragma unroll
    for (int c = 0; c < 8; c++) {
        A[2 * c]     = orow[c * 64 + 2 * lane];
        A[2 * c + 1] = orow[c * 64 + 2 * lane + 1];
    }
    #pragma unroll
    for (int c = 0; c < 8; c++) L[c] = lrow[c * 32 + lane];

    // ---- last index with o1 <= o0 (argmax tie-break: temp=1 iff o1 > o0) ----
    const int base = lane * 4;
    int tz = -1;
    #pragma unroll
    for (int c = 0; c < 8; c++) {
        const int j0 = c * 128 + base;
        float4 a = A[2 * c], b = A[2 * c + 1];
        if (a.y <= a.x) tz = j0;
        if (a.w <= a.z) tz = j0 + 1;
        if (b.y <= b.x) tz = j0 + 2;
        if (b.w <= b.z) tz = j0 + 3;
    }
    int idx = __reduce_max_sync(0xffffffffu, tz);
    if (idx < 0) idx = LL - 1;   // all-continue row: mask all ones anyway

    // ---- masked weighted sum ----
    const float INV_ALPHA = 1.0f / 0.65f;
    float s = 0.0f;
    #pragma unroll
    for (int c = 0; c < 8; c++) {
        const int j0 = c * 128 + base;
        float4 a = A[2 * c], b = A[2 * c + 1];
        float o1v[4] = {a.y, a.w, b.y, b.w};
        int   lv[4]  = {L[c].x, L[c].y, L[c].z, L[c].w};
        #pragma unroll
        for (int k = 0; k < 4; k++) {
            int j = j0 + k;
            if (j <= idx) {
                float jf = (float)j;
                float r = (lv[k] == 1) ? (-1.0f / __log2f(jf + 2.0f))
                                       : ((jf + 1.0f) * INV_ALPHA);
                s += o1v[k] * r;
            }
        }
    }

    // ---- warp sum -> fire-and-forget REDG per row ----
    #pragma unroll
    for (int o = 16; o; o >>= 1) s += __shfl_xor_sync(0xffffffffu, s, o);
    if (lane == 0)
        atomicAdd(&g_acc, (double)s);   // return unused -> REDG, no stall

    // ---- one release-ticket per block; winner finalizes ----
    __syncthreads();                    // all warps' REDGs happen-before ticket
    if (tid == 0) {
        unsigned int v;
        asm volatile("atom.release.gpu.global.add.u32 %0, [%1], %2;"
                     : "=r"(v) : "l"(&g_count), "r"(1u) : "memory");
        if (v == (unsigned)(GRID - 1)) {
            double acc;
            asm volatile("ld.acquire.gpu.global.f64 %0, [%1];"
                         : "=d"(acc) : "l"(&g_acc) : "memory");
            out[0] = (float)(acc * (1.0 / (double)NB));
            g_acc   = 0.0;              // restore for next graph replay
            g_count = 0;
        }
    }
}

extern "C" void kernel_launch(void* const* d_in, const int* in_sizes, int n_in,
                              void* d_out, int out_size) {
    const float4* out4 = (const float4*)d_in[0];
    const int4*   lab4 = (const int4*)d_in[1];
    float* out = (float*)d_out;

    bicut_fused<<<GRID, 256>>>(out4, lab4, out);
}

// round 10
// speedup vs baseline: 1.4740x; 1.4740x over previous
#include <cuda_runtime.h>
#include <cuda_bf16.h>

#define NB 16384
#define LL 1024

__device__ float g_part[NB];   // fully overwritten each call — no init needed

__global__ __launch_bounds__(256) void bicut_rows(
    const float4* __restrict__ out4,   // output as float4: row stride 512
    const int4*   __restrict__ lab4)   // labels (int32) as int4: row stride 256
{
    // PDL: signal early so the dependent finalize grid can be scheduled
    // while our last wave is still streaming.
    cudaTriggerProgrammaticLaunchCompletion();

    const int row = blockIdx.x;
    const int tid = threadIdx.x;
    const int j0  = tid * 4;

    // ---- load output pairs (positions j0..j0+3) and labels up-front ----
    const float4* orow = out4 + (size_t)row * 512;
    float4 a = orow[tid * 2];       // j0, j0+1 : (o0,o1,o0,o1)
    float4 b = orow[tid * 2 + 1];   // j0+2, j0+3
    int4   l = lab4[(size_t)row * 256 + tid];

    // ---- last index with o1 <= o0 (argmax tie-break: temp=1 iff o1 > o0) ----
    int tz = -1;
    if (a.y <= a.x) tz = j0;
    if (a.w <= a.z) tz = j0 + 1;
    if (b.y <= b.x) tz = j0 + 2;
    if (b.w <= b.z) tz = j0 + 3;

    __shared__ int   smax[8];
    __shared__ float ssum[8];

    int m = __reduce_max_sync(0xffffffffu, tz);
    if ((tid & 31) == 0) smax[tid >> 5] = m;
    __syncthreads();
    if (tid < 32) {
        int v = (tid < 8) ? smax[tid] : -1;
        v = __reduce_max_sync(0xffffffffu, v);
        if (tid == 0) smax[0] = v;
    }
    __syncthreads();
    int idx = smax[0];
    if (idx < 0) idx = LL - 1;   // all-ones row: mask is all ones anyway

    // ---- masked weighted sum ----
    const float INV_ALPHA = 1.0f / 0.65f;
    float o1v[4] = {a.y, a.w, b.y, b.w};
    int   lv[4]  = {l.x, l.y, l.z, l.w};

    float s = 0.0f;
    #pragma unroll
    for (int k = 0; k < 4; k++) {
        int j = j0 + k;
        if (j <= idx) {
            float jf = (float)j;
            float r = (lv[k] == 1) ? (-1.0f / __log2f(jf + 2.0f))
                                   : ((jf + 1.0f) * INV_ALPHA);
            s += o1v[k] * r;
        }
    }

    // ---- block sum -> plain per-row store (grid completion orders it) ----
    #pragma unroll
    for (int o = 16; o; o >>= 1) s += __shfl_xor_sync(0xffffffffu, s, o);
    if ((tid & 31) == 0) ssum[tid >> 5] = s;
    __syncthreads();
    if (tid == 0) {
        float t = 0.0f;
        #pragma unroll
        for (int w = 0; w < 8; w++) t += ssum[w];
        g_part[row] = t;
    }
}

__global__ __launch_bounds__(256) void bicut_final(float* __restrict__ out) {
    const int tid = threadIdx.x;

    // Launched early via PDL trigger; block here until the primary grid has
    // fully completed and its stores are visible.
    cudaGridDependencySynchronize();

    const float4* p4 = (const float4*)g_part;   // 4096 float4, L2-resident

    float4 v[16];
    #pragma unroll
    for (int i = 0; i < 16; i++) v[i] = __ldcg(p4 + tid + i * 256);

    float fs = 0.0f;
    #pragma unroll
    for (int i = 0; i < 16; i++)
        fs += (v[i].x + v[i].y) + (v[i].z + v[i].w);

    double acc = (double)fs;
    #pragma unroll
    for (int o = 16; o; o >>= 1) acc += __shfl_xor_sync(0xffffffffu, acc, o);
    __shared__ double dsum[8];
    if ((tid & 31) == 0) dsum[tid >> 5] = acc;
    __syncthreads();
    if (tid == 0) {
        double t = 0.0;
        #pragma unroll
        for (int w = 0; w < 8; w++) t += dsum[w];
        out[0] = (float)(t * (1.0 / (double)NB));
    }
}

extern "C" void kernel_launch(void* const* d_in, const int* in_sizes, int n_in,
                              void* d_out, int out_size) {
    const float4* out4 = (const float4*)d_in[0];
    const int4*   lab4 = (const int4*)d_in[1];
    float* out = (float*)d_out;

    // Primary launched with PDL enabled so its trigger is honored.
    cudaLaunchConfig_t cfg1 = {};
    cfg1.gridDim  = dim3(NB, 1, 1);
    cfg1.blockDim = dim3(256, 1, 1);
    cfg1.stream   = 0;
    cudaLaunchKernelEx(&cfg1, bicut_rows, out4, lab4);

    // Dependent finalize: overlaps launch/preamble with the primary's tail.
    cudaLaunchConfig_t cfg2 = {};
    cfg2.gridDim  = dim3(1, 1, 1);
    cfg2.blockDim = dim3(256, 1, 1);
    cfg2.stream   = 0;
    cudaLaunchAttribute attr[1];
    attr[0].id = cudaLaunchAttributeProgrammaticStreamSerialization;
    attr[0].val.programmaticStreamSerializationAllowed = 1;
    cfg2.attrs = attr;
    cfg2.numAttrs = 1;
    cudaLaunchKernelEx(&cfg2, bicut_final, out);
}

// round 11
// speedup vs baseline: 1.4849x; 1.0074x over previous
#include <cuda_runtime.h>
#include <cuda_bf16.h>

#define NB 16384
#define LL 1024

__device__ double       g_acc   = 0.0;  // 0 at kernel entry; watcher restores
__device__ unsigned int g_count = 0;    // ditto

__global__ __launch_bounds__(256) void bicut_fused(
    const float4* __restrict__ out4,   // output as float4: row stride 512
    const int4*   __restrict__ lab4,   // labels (int32) as int4: row stride 256
    float*        __restrict__ out)
{
    const int row = blockIdx.x;
    const int tid = threadIdx.x;
    const int j0  = tid * 4;

    // ---- load output pairs (positions j0..j0+3) and labels up-front ----
    const float4* orow = out4 + (size_t)row * 512;
    float4 a = orow[tid * 2];       // j0, j0+1 : (o0,o1,o0,o1)
    float4 b = orow[tid * 2 + 1];   // j0+2, j0+3
    int4   l = lab4[(size_t)row * 256 + tid];

    // ---- last index with o1 <= o0 (argmax tie-break: temp=1 iff o1 > o0) ----
    int tz = -1;
    if (a.y <= a.x) tz = j0;
    if (a.w <= a.z) tz = j0 + 1;
    if (b.y <= b.x) tz = j0 + 2;
    if (b.w <= b.z) tz = j0 + 3;

    __shared__ int   smax[8];
    __shared__ float ssum[8];

    int m = __reduce_max_sync(0xffffffffu, tz);
    if ((tid & 31) == 0) smax[tid >> 5] = m;
    __syncthreads();
    if (tid < 32) {
        int v = (tid < 8) ? smax[tid] : -1;
        v = __reduce_max_sync(0xffffffffu, v);
        if (tid == 0) smax[0] = v;
    }
    __syncthreads();
    int idx = smax[0];
    if (idx < 0) idx = LL - 1;   // all-ones row: mask is all ones anyway

    // ---- masked weighted sum ----
    const float INV_ALPHA = 1.0f / 0.65f;
    float o1v[4] = {a.y, a.w, b.y, b.w};
    int   lv[4]  = {l.x, l.y, l.z, l.w};

    float s = 0.0f;
    #pragma unroll
    for (int k = 0; k < 4; k++) {
        int j = j0 + k;
        if (j <= idx) {
            float jf = (float)j;
            float r = (lv[k] == 1) ? (-1.0f / __log2f(jf + 2.0f))
                                   : ((jf + 1.0f) * INV_ALPHA);
            s += o1v[k] * r;
        }
    }

    // ---- block sum -> fire-and-forget REDs (no return => CTA exits free) ----
    #pragma unroll
    for (int o = 16; o; o >>= 1) s += __shfl_xor_sync(0xffffffffu, s, o);
    if ((tid & 31) == 0) ssum[tid >> 5] = s;
    __syncthreads();
    if (tid == 0) {
        float t = 0.0f;
        #pragma unroll
        for (int w = 0; w < 8; w++) t += ssum[w];
        double td = (double)t;
        asm volatile("red.relaxed.gpu.global.add.f64 [%0], %1;"
                     :: "l"(&g_acc), "d"(td) : "memory");
        asm volatile("red.release.gpu.global.add.u32 [%0], %1;"
                     :: "l"(&g_count), "r"(1u) : "memory");
    }

    // ---- watcher: one CTA spins (relaxed, no L1 thrash), then one acquire ----
    if (blockIdx.x == NB - 1 && tid == 0) {
        unsigned int c;
        do {
            __nanosleep(128);
            asm volatile("ld.relaxed.gpu.global.u32 %0, [%1];"
                         : "=r"(c) : "l"(&g_count) : "memory");
        } while (c < (unsigned)NB);
        // single acquire in the whole grid: synchronizes-with every
        // block's release-RED on g_count -> their f64 REDs are visible
        asm volatile("ld.acquire.gpu.global.u32 %0, [%1];"
                     : "=r"(c) : "l"(&g_count) : "memory");
        double acc;
        asm volatile("ld.relaxed.gpu.global.f64 %0, [%1];"
                     : "=d"(acc) : "l"(&g_acc) : "memory");
        out[0] = (float)(acc * (1.0 / (double)NB));
        g_acc   = 0.0;              // restore for next graph replay
        g_count = 0;
    }
}

extern "C" void kernel_launch(void* const* d_in, const int* in_sizes, int n_in,
                              void* d_out, int out_size) {
    const float4* out4 = (const float4*)d_in[0];
    const int4*   lab4 = (const int4*)d_in[1];
    float* out = (float*)d_out;

    bicut_fused<<<NB, 256>>>(out4, lab4, out);
}

// round 12
// speedup vs baseline: 1.4897x; 1.0033x over previous
#include <cuda_runtime.h>
#include <cuda_bf16.h>

#define NB 16384
#define LL 1024
#define RPB 4
#define GRID (NB / RPB)   // 4096

__device__ double       g_acc   = 0.0;  // 0 at kernel entry; watcher restores
__device__ unsigned int g_count = 0;    // ditto

__global__ __launch_bounds__(256) void bicut_fused(
    const float4* __restrict__ out4,   // output as float4: row stride 512
    const int4*   __restrict__ lab4,   // labels (int32) as int4: row stride 256
    float*        __restrict__ out)
{
    const int tid = threadIdx.x;
    const int j0  = tid * 4;
    const int wid = tid >> 5;

    __shared__ int   smax[2][8];   // double-buffered across row iterations
    __shared__ float ssum[8];

    const float INV_ALPHA = 1.0f / 0.65f;
    float sacc = 0.0f;

    #pragma unroll
    for (int r = 0; r < RPB; r++) {
        const int row = blockIdx.x * RPB + r;
        const int p   = r & 1;

        // ---- load this row's output pairs + labels ----
        const float4* orow = out4 + (size_t)row * 512;
        float4 a = orow[tid * 2];       // j0, j0+1 : (o0,o1,o0,o1)
        float4 b = orow[tid * 2 + 1];   // j0+2, j0+3
        int4   l = lab4[(size_t)row * 256 + tid];

        // ---- last index with o1 <= o0 (argmax tie: temp=1 iff o1 > o0) ----
        int tz = -1;
        if (a.y <= a.x) tz = j0;
        if (a.w <= a.z) tz = j0 + 1;
        if (b.y <= b.x) tz = j0 + 2;
        if (b.w <= b.z) tz = j0 + 3;

        int m = __reduce_max_sync(0xffffffffu, tz);
        if ((tid & 31) == 0) smax[p][wid] = m;
        __syncthreads();
        if (tid < 32) {
            int v = (tid < 8) ? smax[p][tid] : -1;
            v = __reduce_max_sync(0xffffffffu, v);
            if (tid == 0) smax[p][0] = v;
        }
        __syncthreads();
        int idx = smax[p][0];
        if (idx < 0) idx = LL - 1;   // all-continue row: mask all ones anyway

        // ---- masked weighted sum, accumulated across the 4 rows ----
        float o1v[4] = {a.y, a.w, b.y, b.w};
        int   lv[4]  = {l.x, l.y, l.z, l.w};
        #pragma unroll
        for (int k = 0; k < 4; k++) {
            int j = j0 + k;
            if (j <= idx) {
                float jf = (float)j;
                float rr = (lv[k] == 1) ? (-1.0f / __log2f(jf + 2.0f))
                                        : ((jf + 1.0f) * INV_ALPHA);
                sacc += o1v[k] * rr;
            }
        }
    }

    // ---- one block sum for all 4 rows ----
    #pragma unroll
    for (int o = 16; o; o >>= 1) sacc += __shfl_xor_sync(0xffffffffu, sacc, o);
    if ((tid & 31) == 0) ssum[wid] = sacc;
    __syncthreads();
    if (tid == 0) {
        float t = 0.0f;
        #pragma unroll
        for (int w = 0; w < 8; w++) t += ssum[w];
        double td = (double)t;
        // fire-and-forget accumulate, then ONE release ticket per 4 rows
        asm volatile("red.relaxed.gpu.global.add.f64 [%0], %1;"
                     :: "l"(&g_acc), "d"(td) : "memory");
        asm volatile("red.release.gpu.global.add.u32 [%0], %1;"
                     :: "l"(&g_count), "r"(1u) : "memory");
    }

    // ---- watcher: spin relaxed (no L1 thrash), one acquire, finalize ----
    if (blockIdx.x == GRID - 1 && tid == 0) {
        unsigned int c;
        do {
            __nanosleep(128);
            asm volatile("ld.relaxed.gpu.global.u32 %0, [%1];"
                         : "=r"(c) : "l"(&g_count) : "memory");
        } while (c < (unsigned)GRID);
        asm volatile("ld.acquire.gpu.global.u32 %0, [%1];"
                     : "=r"(c) : "l"(&g_count) : "memory");
        double acc;
        asm volatile("ld.relaxed.gpu.global.f64 %0, [%1];"
                     : "=d"(acc) : "l"(&g_acc) : "memory");
        out[0] = (float)(acc * (1.0 / (double)NB));
        g_acc   = 0.0;              // restore for next graph replay
        g_count = 0;
    }
}

extern "C" void kernel_launch(void* const* d_in, const int* in_sizes, int n_in,
                              void* d_out, int out_size) {
    const float4* out4 = (const float4*)d_in[0];
    const int4*   lab4 = (const int4*)d_in[1];
    float* out = (float*)d_out;

    bicut_fused<<<GRID, 256>>>(out4, lab4, out);
}

// round 13
// speedup vs baseline: 1.4910x; 1.0008x over previous
#include <cuda_runtime.h>
#include <cuda_bf16.h>

#define NB 16384
#define LL 1024

__device__ double       g_acc   = 0.0;  // 0 at kernel entry; watcher restores
__device__ unsigned int g_count = 0;    // ditto

__global__ __launch_bounds__(256) void bicut_fused(
    const float4* __restrict__ out4,   // output as float4: row stride 512
    const int2*   __restrict__ lab2,   // labels (int32) as int2: row stride 512
    float*        __restrict__ out)
{
    const int row = blockIdx.x;
    const int tid = threadIdx.x;

    // ---- perfectly-coalesced, evict-first loads ----
    // thread t: float4 #t   -> j = 2t, 2t+1      (lane-contiguous, 4 lines/LDG)
    //           float4 #t+256 -> j = 2t+512, 2t+513
    const float4* orow = out4 + (size_t)row * 512;
    const int2*   lrow = lab2 + (size_t)row * 512;
    float4 a  = __ldcs(orow + tid);
    float4 b  = __ldcs(orow + tid + 256);
    int2   la = __ldcs(lrow + tid);
    int2   lb = __ldcs(lrow + tid + 256);

    const int ja = 2 * tid;        // a covers ja, ja+1
    const int jb = ja + 512;       // b covers jb, jb+1

    // ---- last index with o1 <= o0 (argmax tie-break: temp=1 iff o1 > o0) ----
    int tz = -1;
    if (a.y <= a.x) tz = ja;
    if (a.w <= a.z) tz = ja + 1;
    if (b.y <= b.x) tz = jb;
    if (b.w <= b.z) tz = jb + 1;

    __shared__ int   smax[8];
    __shared__ float ssum[8];

    int m = __reduce_max_sync(0xffffffffu, tz);
    if ((tid & 31) == 0) smax[tid >> 5] = m;
    __syncthreads();
    if (tid < 32) {
        int v = (tid < 8) ? smax[tid] : -1;
        v = __reduce_max_sync(0xffffffffu, v);
        if (tid == 0) smax[0] = v;
    }
    __syncthreads();
    int idx = smax[0];
    if (idx < 0) idx = LL - 1;   // all-continue row: mask is all ones anyway

    // ---- masked weighted sum ----
    const float INV_ALPHA = 1.0f / 0.65f;
    float o1v[4] = {a.y, a.w, b.y, b.w};
    int   jv[4]  = {ja, ja + 1, jb, jb + 1};
    int   lv[4]  = {la.x, la.y, lb.x, lb.y};

    float s = 0.0f;
    #pragma unroll
    for (int k = 0; k < 4; k++) {
        int j = jv[k];
        if (j <= idx) {
            float jf = (float)j;
            float r = (lv[k] == 1) ? (-1.0f / __log2f(jf + 2.0f))
                                   : ((jf + 1.0f) * INV_ALPHA);
            s += o1v[k] * r;
        }
    }

    // ---- block sum -> fire-and-forget REDs (CTA exits without waiting) ----
    #pragma unroll
    for (int o = 16; o; o >>= 1) s += __shfl_xor_sync(0xffffffffu, s, o);
    if ((tid & 31) == 0) ssum[tid >> 5] = s;
    __syncthreads();
    if (tid == 0) {
        float t = 0.0f;
        #pragma unroll
        for (int w = 0; w < 8; w++) t += ssum[w];
        double td = (double)t;
        asm volatile("red.relaxed.gpu.global.add.f64 [%0], %1;"
                     :: "l"(&g_acc), "d"(td) : "memory");
        asm volatile("red.release.gpu.global.add.u32 [%0], %1;"
                     :: "l"(&g_count), "r"(1u) : "memory");
    }

    // ---- watcher: spin relaxed (no L1 thrash), one acquire, finalize ----
    if (blockIdx.x == NB - 1 && tid == 0) {
        unsigned int c;
        do {
            __nanosleep(128);
            asm volatile("ld.relaxed.gpu.global.u32 %0, [%1];"
                         : "=r"(c) : "l"(&g_count) : "memory");
        } while (c < (unsigned)NB);
        asm volatile("ld.acquire.gpu.global.u32 %0, [%1];"
                     : "=r"(c) : "l"(&g_count) : "memory");
        double acc;
        asm volatile("ld.relaxed.gpu.global.f64 %0, [%1];"
                     : "=d"(acc) : "l"(&g_acc) : "memory");
        out[0] = (float)(acc * (1.0 / (double)NB));
        g_acc   = 0.0;              // restore for next graph replay
        g_count = 0;
    }
}

extern "C" void kernel_launch(void* const* d_in, const int* in_sizes, int n_in,
                              void* d_out, int out_size) {
    const float4* out4 = (const float4*)d_in[0];
    const int2*   lab2 = (const int2*)d_in[1];
    float* out = (float*)d_out;

    bicut_fused<<<NB, 256>>>(out4, lab2, out);
}

// round 14
// speedup vs baseline: 1.6302x; 1.0934x over previous
#include <cuda_runtime.h>
#include <cuda_bf16.h>

#define NB 16384
#define LL 1024

// Single packed accumulator: bits[0:15)=block count, bits[15:64)=sum in Q16
// fixed point (mod 2^49, two's complement). 0 at kernel entry; watcher restores.
__device__ unsigned long long g_pack = 0ULL;

__global__ __launch_bounds__(256) void bicut_fused(
    const float4* __restrict__ out4,   // output as float4: row stride 512
    const int4*   __restrict__ lab4,   // labels (int32) as int4: row stride 256
    float*        __restrict__ out)
{
    const int row = blockIdx.x;
    const int tid = threadIdx.x;
    const int j0  = tid * 4;

    // ---- load output pairs (positions j0..j0+3) and labels up-front ----
    const float4* orow = out4 + (size_t)row * 512;
    float4 a = orow[tid * 2];       // j0, j0+1 : (o0,o1,o0,o1)
    float4 b = orow[tid * 2 + 1];   // j0+2, j0+3
    int4   l = lab4[(size_t)row * 256 + tid];

    // ---- last index with o1 <= o0 (argmax tie-break: temp=1 iff o1 > o0) ----
    int tz = -1;
    if (a.y <= a.x) tz = j0;
    if (a.w <= a.z) tz = j0 + 1;
    if (b.y <= b.x) tz = j0 + 2;
    if (b.w <= b.z) tz = j0 + 3;

    __shared__ int   smax[8];
    __shared__ float ssum[8];

    int m = __reduce_max_sync(0xffffffffu, tz);
    if ((tid & 31) == 0) smax[tid >> 5] = m;
    __syncthreads();
    if (tid < 32) {
        int v = (tid < 8) ? smax[tid] : -1;
        v = __reduce_max_sync(0xffffffffu, v);
        if (tid == 0) smax[0] = v;
    }
    __syncthreads();
    int idx = smax[0];
    if (idx < 0) idx = LL - 1;   // all-continue row: mask is all ones anyway

    // ---- masked weighted sum ----
    const float INV_ALPHA = 1.0f / 0.65f;
    float o1v[4] = {a.y, a.w, b.y, b.w};
    int   lv[4]  = {l.x, l.y, l.z, l.w};

    float s = 0.0f;
    #pragma unroll
    for (int k = 0; k < 4; k++) {
        int j = j0 + k;
        if (j <= idx) {
            float jf = (float)j;
            float r = (lv[k] == 1) ? (-1.0f / __log2f(jf + 2.0f))
                                   : ((jf + 1.0f) * INV_ALPHA);
            s += o1v[k] * r;
        }
    }

    // ---- block sum -> ONE relaxed RED carrying (count | Q16 sum) ----
    #pragma unroll
    for (int o = 16; o; o >>= 1) s += __shfl_xor_sync(0xffffffffu, s, o);
    if ((tid & 31) == 0) ssum[tid >> 5] = s;
    __syncthreads();
    if (tid == 0) {
        float t = 0.0f;
        #pragma unroll
        for (int w = 0; w < 8; w++) t += ssum[w];
        long long q = llrintf(t * 65536.0f);               // Q16 fixed point
        unsigned long long v = ((unsigned long long)q << 15) + 1ULL;
        asm volatile("red.relaxed.gpu.global.add.u64 [%0], %1;"
                     :: "l"(&g_pack), "l"(v) : "memory");   // fire-and-forget
    }

    // ---- watcher: poll the single word; its value IS the complete result ----
    if (blockIdx.x == NB - 1 && tid == 0) {
        unsigned long long v;
        do {
            __nanosleep(128);
            asm volatile("ld.relaxed.gpu.global.u64 %0, [%1];"
                         : "=l"(v) : "l"(&g_pack) : "memory");
        } while ((v & 0x7FFFULL) < (unsigned long long)NB);
        // count==NB => all 16384 adds are in this very value (single-word atomicity)
        long long q = ((long long)v) >> 15;   // sign bit 48 sits at bit 63
        out[0] = (float)((double)q * (1.0 / (65536.0 * (double)NB)));
        g_pack = 0ULL;                        // restore for next graph replay
    }
}

extern "C" void kernel_launch(void* const* d_in, const int* in_sizes, int n_in,
                              void* d_out, int out_size) {
    const float4* out4 = (const float4*)d_in[0];
    const int4*   lab4 = (const int4*)d_in[1];
    float* out = (float*)d_out;

    bicut_fused<<<NB, 256>>>(out4, lab4, out);
}

// round 15
// speedup vs baseline: 1.6464x; 1.0100x over previous
#include <cuda_runtime.h>
#include <cuda_bf16.h>

#define NB 16384
#define LL 1024

// Single packed accumulator: bits[0:15)=block count, bits[15:64)=sum in Q16
// fixed point (mod 2^49, two's complement). 0 at kernel entry; watcher restores.
__device__ unsigned long long g_pack = 0ULL;

__global__ __launch_bounds__(256) void bicut_fused(
    const float4* __restrict__ out4,   // output as float4: row stride 512
    const int2*   __restrict__ lab2,   // labels (int32) as int2: row stride 512
    float*        __restrict__ out)
{
    const int row = blockIdx.x;
    const int tid = threadIdx.x;

    // ---- perfectly-coalesced, evict-first loads ----
    // thread t: float4 #t     -> j = 2t, 2t+1       (lane-contiguous)
    //           float4 #t+256 -> j = 2t+512, 2t+513
    const float4* orow = out4 + (size_t)row * 512;
    const int2*   lrow = lab2 + (size_t)row * 512;
    float4 a  = __ldcs(orow + tid);
    float4 b  = __ldcs(orow + tid + 256);
    int2   la = __ldcs(lrow + tid);
    int2   lb = __ldcs(lrow + tid + 256);

    const int ja = 2 * tid;        // a covers ja, ja+1
    const int jb = ja + 512;       // b covers jb, jb+1

    // ---- last index with o1 <= o0 (argmax tie-break: temp=1 iff o1 > o0) ----
    int tz = -1;
    if (a.y <= a.x) tz = ja;
    if (a.w <= a.z) tz = ja + 1;
    if (b.y <= b.x) tz = jb;
    if (b.w <= b.z) tz = jb + 1;

    __shared__ int   smax[8];
    __shared__ float ssum[8];

    int m = __reduce_max_sync(0xffffffffu, tz);
    if ((tid & 31) == 0) smax[tid >> 5] = m;
    __syncthreads();
    if (tid < 32) {
        int v = (tid < 8) ? smax[tid] : -1;
        v = __reduce_max_sync(0xffffffffu, v);
        if (tid == 0) smax[0] = v;
    }
    __syncthreads();
    int idx = smax[0];
    if (idx < 0) idx = LL - 1;   // all-continue row: mask is all ones anyway

    // ---- masked weighted sum ----
    const float INV_ALPHA = 1.0f / 0.65f;
    float o1v[4] = {a.y, a.w, b.y, b.w};
    int   jv[4]  = {ja, ja + 1, jb, jb + 1};
    int   lv[4]  = {la.x, la.y, lb.x, lb.y};

    float s = 0.0f;
    #pragma unroll
    for (int k = 0; k < 4; k++) {
        int j = jv[k];
        if (j <= idx) {
            float jf = (float)j;
            float r = (lv[k] == 1) ? (-1.0f / __log2f(jf + 2.0f))
                                   : ((jf + 1.0f) * INV_ALPHA);
            s += o1v[k] * r;
        }
    }

    // ---- block sum -> ONE relaxed RED carrying (count | Q16 sum) ----
    #pragma unroll
    for (int o = 16; o; o >>= 1) s += __shfl_xor_sync(0xffffffffu, s, o);
    if ((tid & 31) == 0) ssum[tid >> 5] = s;
    __syncthreads();
    if (tid == 0) {
        float t = 0.0f;
        #pragma unroll
        for (int w = 0; w < 8; w++) t += ssum[w];
        long long q = llrintf(t * 65536.0f);               // Q16 fixed point
        unsigned long long v = ((unsigned long long)q << 15) + 1ULL;
        asm volatile("red.relaxed.gpu.global.add.u64 [%0], %1;"
                     :: "l"(&g_pack), "l"(v) : "memory");   // fire-and-forget
    }

    // ---- watcher: poll the single word; its value IS the complete result ----
    if (blockIdx.x == NB - 1 && tid == 0) {
        unsigned long long v;
        do {
            __nanosleep(64);
            asm volatile("ld.relaxed.gpu.global.u64 %0, [%1];"
                         : "=l"(v) : "l"(&g_pack) : "memory");
        } while ((v & 0x7FFFULL) < (unsigned long long)NB);
        // count==NB => all 16384 adds are in this very value (single-word atomicity)
        long long q = ((long long)v) >> 15;   // sign bit 48 sits at bit 63
        out[0] = (float)((double)q * (1.0 / (65536.0 * (double)NB)));
        g_pack = 0ULL;                        // restore for next graph replay
    }
}

extern "C" void kernel_launch(void* const* d_in, const int* in_sizes, int n_in,
                              void* d_out, int out_size) {
    const float4* out4 = (const float4*)d_in[0];
    const int2*   lab2 = (const int2*)d_in[1];
    float* out = (float*)d_out;

    bicut_fused<<<NB, 256>>>(out4, lab2, out);
}